// round 4
// baseline (speedup 1.0000x reference)
#include <cuda_runtime.h>
#include <math.h>

// Problem constants
#define BATCH 4
#define SEQ   2048
#define DIM   1024
#define NROWS (BATCH * SEQ)          // 8192

// Scratch (device globals: allocation-free)
__device__ float g_q[(size_t)BATCH * SEQ * DIM];
__device__ float g_k[(size_t)BATCH * SEQ * DIM];
__device__ float g_v[(size_t)BATCH * SEQ * DIM];
__device__ float g_s[(size_t)BATCH * SEQ * SEQ];

// ---------------------------------------------------------------------------
// Tiled fp32 GEMM: C = alpha * A * op(B) + bias
//   TRANSB=true : A[M,K] rm, B[N,K] rm  -> C = A * B^T   (QKV, scores)
//   TRANSB=false: A[M,K] rm, B[K,N] rm  -> C = A * B     (attn * V)
// BM=BN=128, BK=16, 256 threads, 8x8 per thread (split 4+4 fragments).
// All dims assumed multiples of tile sizes (true for this problem).
// ---------------------------------------------------------------------------
#define BM 128
#define BN 128
#define BK 16

template <bool TRANSB>
__global__ void __launch_bounds__(256, 2) gemm_kernel(
    const float* __restrict__ A, const float* __restrict__ B,
    const float* __restrict__ bias, float* __restrict__ C,
    int lda, int ldb, int ldc, int K,
    long sA, long sB, long sC, float alpha)
{
    __shared__ float As[BK][BM + 4];
    __shared__ float Bs[BK][BN + 4];

    const float* Ab = A + (long)blockIdx.z * sA + (long)blockIdx.x * BM * lda;
    const float* Bb;
    if (TRANSB) Bb = B + (long)blockIdx.z * sB + (long)blockIdx.y * BN * ldb;
    else        Bb = B + (long)blockIdx.z * sB + (long)blockIdx.y * BN;
    float* Cb = C + (long)blockIdx.z * sC + (long)blockIdx.x * BM * ldc
                  + (long)blockIdx.y * BN;

    const int tid = threadIdx.x;
    const int tx  = tid & 15;   // 0..15 -> output cols
    const int ty  = tid >> 4;   // 0..15 -> output rows

    float acc[8][8];
    #pragma unroll
    for (int i = 0; i < 8; i++)
        #pragma unroll
        for (int j = 0; j < 8; j++) acc[i][j] = 0.0f;

    for (int k0 = 0; k0 < K; k0 += BK) {
        // ---- load A tile (128 x 16), store transposed As[k][m] ----
        #pragma unroll
        for (int i = 0; i < 2; i++) {
            int idx4 = tid + i * 256;          // 0..511 float4 slots
            int row  = idx4 >> 2;              // 0..127
            int c4   = (idx4 & 3) * 4;         // 0,4,8,12
            float4 f = *(const float4*)&Ab[(long)row * lda + k0 + c4];
            As[c4 + 0][row] = f.x;
            As[c4 + 1][row] = f.y;
            As[c4 + 2][row] = f.z;
            As[c4 + 3][row] = f.w;
        }
        // ---- load B tile -> Bs[k][n] ----
        if (TRANSB) {
            #pragma unroll
            for (int i = 0; i < 2; i++) {
                int idx4 = tid + i * 256;
                int row  = idx4 >> 2;          // 0..127 (n index)
                int c4   = (idx4 & 3) * 4;     // k offset
                float4 f = *(const float4*)&Bb[(long)row * ldb + k0 + c4];
                Bs[c4 + 0][row] = f.x;
                Bs[c4 + 1][row] = f.y;
                Bs[c4 + 2][row] = f.z;
                Bs[c4 + 3][row] = f.w;
            }
        } else {
            #pragma unroll
            for (int i = 0; i < 2; i++) {
                int idx4 = tid + i * 256;
                int krow = idx4 >> 5;          // 0..15
                int c4   = (idx4 & 31) * 4;    // 0..124
                float4 f = *(const float4*)&Bb[(long)(k0 + krow) * ldb + c4];
                *(float4*)&Bs[krow][c4] = f;
            }
        }
        __syncthreads();

        // ---- compute ----
        #pragma unroll
        for (int kk = 0; kk < BK; kk++) {
            float a[8], b[8];
            *(float4*)&a[0] = *(const float4*)&As[kk][ty * 4];
            *(float4*)&a[4] = *(const float4*)&As[kk][64 + ty * 4];
            *(float4*)&b[0] = *(const float4*)&Bs[kk][tx * 4];
            *(float4*)&b[4] = *(const float4*)&Bs[kk][64 + tx * 4];
            #pragma unroll
            for (int i = 0; i < 8; i++)
                #pragma unroll
                for (int j = 0; j < 8; j++)
                    acc[i][j] = fmaf(a[i], b[j], acc[i][j]);
        }
        __syncthreads();
    }

    // ---- epilogue ----
    const float* biasb = bias ? bias + (long)blockIdx.y * BN : nullptr;
    #pragma unroll
    for (int i = 0; i < 8; i++) {
        int row = (i < 4) ? (ty * 4 + i) : (64 + ty * 4 + (i - 4));
        #pragma unroll
        for (int half = 0; half < 2; half++) {
            int col = (half == 0) ? (tx * 4) : (64 + tx * 4);
            float4 o;
            o.x = acc[i][half * 4 + 0] * alpha;
            o.y = acc[i][half * 4 + 1] * alpha;
            o.z = acc[i][half * 4 + 2] * alpha;
            o.w = acc[i][half * 4 + 3] * alpha;
            if (biasb) {
                o.x += biasb[col + 0];
                o.y += biasb[col + 1];
                o.z += biasb[col + 2];
                o.w += biasb[col + 3];
            }
            *(float4*)&Cb[(long)row * ldc + col] = o;
        }
    }
}

// ---------------------------------------------------------------------------
// Row softmax over g_s: one block per row of 2048, 256 threads, 8 vals/thread.
// ---------------------------------------------------------------------------
__global__ void __launch_bounds__(256) softmax_kernel(float* __restrict__ S)
{
    __shared__ float red[8];
    __shared__ float bcast;

    long row = blockIdx.x;
    float4* p4 = (float4*)(S + row * (long)SEQ);
    const int tid  = threadIdx.x;
    const int lane = tid & 31;
    const int wid  = tid >> 5;

    float4 v0 = p4[tid];
    float4 v1 = p4[tid + 256];

    // row max
    float m = fmaxf(fmaxf(fmaxf(v0.x, v0.y), fmaxf(v0.z, v0.w)),
                    fmaxf(fmaxf(v1.x, v1.y), fmaxf(v1.z, v1.w)));
    #pragma unroll
    for (int o = 16; o > 0; o >>= 1) m = fmaxf(m, __shfl_xor_sync(0xffffffffu, m, o));
    if (lane == 0) red[wid] = m;
    __syncthreads();
    if (wid == 0) {
        float x = (lane < 8) ? red[lane] : -3.4e38f;
        #pragma unroll
        for (int o = 4; o > 0; o >>= 1) x = fmaxf(x, __shfl_xor_sync(0xffffffffu, x, o));
        if (lane == 0) bcast = x;
    }
    __syncthreads();
    m = bcast;
    __syncthreads();

    // exp + sum
    v0.x = __expf(v0.x - m); v0.y = __expf(v0.y - m);
    v0.z = __expf(v0.z - m); v0.w = __expf(v0.w - m);
    v1.x = __expf(v1.x - m); v1.y = __expf(v1.y - m);
    v1.z = __expf(v1.z - m); v1.w = __expf(v1.w - m);
    float s = (v0.x + v0.y + v0.z + v0.w) + (v1.x + v1.y + v1.z + v1.w);
    #pragma unroll
    for (int o = 16; o > 0; o >>= 1) s += __shfl_xor_sync(0xffffffffu, s, o);
    if (lane == 0) red[wid] = s;
    __syncthreads();
    if (wid == 0) {
        float x = (lane < 8) ? red[lane] : 0.0f;
        #pragma unroll
        for (int o = 4; o > 0; o >>= 1) x += __shfl_xor_sync(0xffffffffu, x, o);
        if (lane == 0) bcast = x;
    }
    __syncthreads();
    float inv = 1.0f / bcast;

    v0.x *= inv; v0.y *= inv; v0.z *= inv; v0.w *= inv;
    v1.x *= inv; v1.y *= inv; v1.z *= inv; v1.w *= inv;
    p4[tid]       = v0;
    p4[tid + 256] = v1;
}

// ---------------------------------------------------------------------------
// kernel_launch
// inputs (metadata order): x, Wq, bq, Wk, bk, Wv, bv
// ---------------------------------------------------------------------------
extern "C" void kernel_launch(void* const* d_in, const int* in_sizes, int n_in,
                              void* d_out, int out_size)
{
    const float* x  = (const float*)d_in[0];
    const float* Wq = (const float*)d_in[1];
    const float* bq = (const float*)d_in[2];
    const float* Wk = (const float*)d_in[3];
    const float* bk = (const float*)d_in[4];
    const float* Wv = (const float*)d_in[5];
    const float* bv = (const float*)d_in[6];
    float* out = (float*)d_out;

    float *q, *k, *v, *sc;
    cudaGetSymbolAddress((void**)&q,  g_q);
    cudaGetSymbolAddress((void**)&k,  g_k);
    cudaGetSymbolAddress((void**)&v,  g_v);
    cudaGetSymbolAddress((void**)&sc, g_s);

    const float scale = 1.0f / 32.0f;   // 1/sqrt(1024)

    // QKV projections: [8192,1024] x [1024,1024]^T + bias
    {
        dim3 grid(NROWS / BM, DIM / BN, 1);
        gemm_kernel<true><<<grid, 256>>>(x, Wq, bq, q, DIM, DIM, DIM, DIM, 0, 0, 0, 1.0f);
        gemm_kernel<true><<<grid, 256>>>(x, Wk, bk, k, DIM, DIM, DIM, DIM, 0, 0, 0, 1.0f);
        gemm_kernel<true><<<grid, 256>>>(x, Wv, bv, v, DIM, DIM, DIM, DIM, 0, 0, 0, 1.0f);
    }

    // Scores: per batch [2048,1024] x [1024,2048]^T * scale
    {
        dim3 grid(SEQ / BM, SEQ / BN, BATCH);
        gemm_kernel<true><<<grid, 256>>>(q, k, nullptr, sc,
                                         DIM, DIM, SEQ, DIM,
                                         (long)SEQ * DIM, (long)SEQ * DIM,
                                         (long)SEQ * SEQ, scale);
    }

    // Softmax rows
    softmax_kernel<<<BATCH * SEQ, 256>>>(sc);

    // Out: per batch [2048,2048] x [2048,1024]
    {
        dim3 grid(SEQ / BM, DIM / BN, BATCH);
        gemm_kernel<false><<<grid, 256>>>(sc, v, nullptr, out,
                                          SEQ, DIM, DIM, SEQ,
                                          (long)SEQ * SEQ, (long)SEQ * DIM,
                                          (long)SEQ * DIM, 1.0f);
    }
}

// round 6
// speedup vs baseline: 1.8894x; 1.8894x over previous
#include <cuda_runtime.h>
#include <cuda_bf16.h>
#include <stdint.h>
#include <math.h>

// ---------------------------------------------------------------------------
// Problem constants
// ---------------------------------------------------------------------------
#define BATCH 4
#define SEQ   2048
#define DIM   1024
#define NROWS (BATCH * SEQ)          // 8192

// ---------------------------------------------------------------------------
// Scratch (device globals: allocation-free)
// ---------------------------------------------------------------------------
__device__ __align__(128) __nv_bfloat16 g_xhi[(size_t)NROWS * DIM];
__device__ __align__(128) __nv_bfloat16 g_xlo[(size_t)NROWS * DIM];
__device__ __align__(128) __nv_bfloat16 g_whi[(size_t)3 * DIM * DIM];
__device__ __align__(128) __nv_bfloat16 g_wlo[(size_t)3 * DIM * DIM];
__device__ __align__(128) float         g_q[(size_t)NROWS * DIM];
__device__ __align__(128) float         g_k[(size_t)NROWS * DIM];
__device__ __align__(128) float         g_v[(size_t)NROWS * DIM];
__device__ __align__(128) __nv_bfloat16 g_qhi[(size_t)NROWS * DIM];
__device__ __align__(128) __nv_bfloat16 g_qlo[(size_t)NROWS * DIM];
__device__ __align__(128) __nv_bfloat16 g_khi[(size_t)NROWS * DIM];
__device__ __align__(128) __nv_bfloat16 g_klo[(size_t)NROWS * DIM];
__device__ __align__(128) __nv_bfloat16 g_vthi[(size_t)BATCH * DIM * SEQ];
__device__ __align__(128) __nv_bfloat16 g_vtlo[(size_t)BATCH * DIM * SEQ];
__device__ __align__(128) float         g_s[(size_t)BATCH * SEQ * SEQ];
__device__ __align__(128) __nv_bfloat16 g_ahi[(size_t)BATCH * SEQ * SEQ];
__device__ __align__(128) __nv_bfloat16 g_alo[(size_t)BATCH * SEQ * SEQ];

// ---------------------------------------------------------------------------
// PTX helpers (baseline PTX only — NO tcgen05: harness ptxas targets sm_103
// without the 'a' feature set)
// ---------------------------------------------------------------------------
__device__ __forceinline__ uint32_t smem_u32(const void* p) {
    uint32_t a;
    asm("{ .reg .u64 t; cvta.to.shared.u64 t, %1; cvt.u32.u64 %0, t; }"
        : "=r"(a) : "l"(p));
    return a;
}

__device__ __forceinline__ void ldmatrix_x4(uint32_t& r0, uint32_t& r1,
                                            uint32_t& r2, uint32_t& r3,
                                            uint32_t addr) {
    asm volatile("ldmatrix.sync.aligned.m8n8.x4.shared.b16 {%0,%1,%2,%3}, [%4];"
                 : "=r"(r0), "=r"(r1), "=r"(r2), "=r"(r3) : "r"(addr));
}

__device__ __forceinline__ void mma_bf16(float* d, const uint32_t* a,
                                         const uint32_t* b) {
    asm volatile(
        "mma.sync.aligned.m16n8k16.row.col.f32.bf16.bf16.f32 "
        "{%0,%1,%2,%3}, {%4,%5,%6,%7}, {%8,%9}, {%0,%1,%2,%3};"
        : "+f"(d[0]), "+f"(d[1]), "+f"(d[2]), "+f"(d[3])
        : "r"(a[0]), "r"(a[1]), "r"(a[2]), "r"(a[3]),
          "r"(b[0]), "r"(b[1]));
}

// ---------------------------------------------------------------------------
// bf16x3 GEMM via mma.sync: C[m,n] = alpha * sum_k A[m,k]*B[n,k] + bias[n]
//   A ~ Ahi+Alo, B ~ Bhi+Blo; 3 segments (hi,hi),(hi,lo),(lo,hi) accumulate
//   into one fp32 accumulator (K logically tripled).
//   A rm [M,K] bf16, B rm [N,K] bf16, C rm [M,N] fp32.
//   Tile 128x128, BK=32, 256 thr = 8 warps (2m x 4n), warp tile 64x32.
//   smem rows padded to 40 elems (80B): 16B-aligned, ldmatrix conflict-free.
// ---------------------------------------------------------------------------
#define PAD   40
#define TSTRD (128 * PAD)   // elems per stage per matrix

__global__ void __launch_bounds__(256)
gemm_bf16x3(const __nv_bfloat16* __restrict__ Ahi, const __nv_bfloat16* __restrict__ Alo,
            const __nv_bfloat16* __restrict__ Bhi, const __nv_bfloat16* __restrict__ Blo,
            const float* __restrict__ bias, float* __restrict__ C,
            int K, int N, long sA, long sB, long sC, float alpha)
{
    __shared__ __nv_bfloat16 sA_t[2][TSTRD];
    __shared__ __nv_bfloat16 sB_t[2][TSTRD];

    const int tid  = threadIdx.x;
    const int lane = tid & 31;
    const int wid  = tid >> 5;
    const int wm   = (wid >> 2) * 64;   // warp m origin (0 or 64)
    const int wn   = (wid & 3) * 32;    // warp n origin (0,32,64,96)

    const long m0 = (long)blockIdx.x * 128;
    const long n0 = (long)blockIdx.y * 128;
    const int  z  = blockIdx.z;
    const int  KT = K >> 5;             // 32-wide K tiles per segment
    const int  NT = 3 * KT;

    const __nv_bfloat16* Ah = Ahi + (long)z * sA;
    const __nv_bfloat16* Al = Alo + (long)z * sA;
    const __nv_bfloat16* Bh = Bhi + (long)z * sB;
    const __nv_bfloat16* Bl = Blo + (long)z * sB;

    const uint32_t sa_base = smem_u32(sA_t);
    const uint32_t sb_base = smem_u32(sB_t);

    float acc[4][4][4];
    #pragma unroll
    for (int i = 0; i < 4; i++)
        #pragma unroll
        for (int j = 0; j < 4; j++)
            #pragma unroll
            for (int r = 0; r < 4; r++) acc[i][j][r] = 0.0f;

    uint4 ra[2], rb[2];

    // global load of tile t into regs
    auto ldg_tile = [&](int t) {
        const int seg = t / KT;
        const long kk = (long)(t - seg * KT) << 5;
        const __nv_bfloat16* Ap = (seg < 2)  ? Ah : Al;
        const __nv_bfloat16* Bp = (seg != 1) ? Bh : Bl;
        #pragma unroll
        for (int i = 0; i < 2; i++) {
            const int id  = tid + i * 256;   // 0..511
            const int row = id >> 2;         // 0..127
            const int j   = id & 3;          // k-chunk of 8
            ra[i] = *(const uint4*)(Ap + (m0 + row) * K + kk + j * 8);
            rb[i] = *(const uint4*)(Bp + (n0 + row) * K + kk + j * 8);
        }
    };
    auto sts_tile = [&](int buf) {
        __nv_bfloat16* da = sA_t[buf];
        __nv_bfloat16* db = sB_t[buf];
        #pragma unroll
        for (int i = 0; i < 2; i++) {
            const int id  = tid + i * 256;
            const int row = id >> 2;
            const int j   = id & 3;
            *(uint4*)(da + row * PAD + j * 8) = ra[i];
            *(uint4*)(db + row * PAD + j * 8) = rb[i];
        }
    };

    // compute one BK=32 tile from smem buffer
    auto compute = [&](int buf) {
        const uint32_t ab = sa_base + buf * (TSTRD * 2);
        const uint32_t bb = sb_base + buf * (TSTRD * 2);
        #pragma unroll
        for (int ks = 0; ks < 2; ks++) {
            uint32_t af[4][4], bf[4][2];
            // A fragments: 4 m-tiles of 16
            #pragma unroll
            for (int mt = 0; mt < 4; mt++) {
                const int row  = wm + mt * 16 + (lane & 15);
                const int koff = ks * 16 + ((lane >> 4) << 3);
                ldmatrix_x4(af[mt][0], af[mt][1], af[mt][2], af[mt][3],
                            ab + (row * PAD + koff) * 2);
            }
            // B fragments: 4 n-tiles of 8, two x4 loads
            #pragma unroll
            for (int h = 0; h < 2; h++) {
                const int row  = wn + h * 16 + (lane & 7) + ((lane >> 4) << 3);
                const int koff = ks * 16 + ((lane >> 3) & 1) * 8;
                ldmatrix_x4(bf[h * 2][0], bf[h * 2][1],
                            bf[h * 2 + 1][0], bf[h * 2 + 1][1],
                            bb + (row * PAD + koff) * 2);
            }
            #pragma unroll
            for (int mt = 0; mt < 4; mt++)
                #pragma unroll
                for (int nt = 0; nt < 4; nt++)
                    mma_bf16(acc[mt][nt], af[mt], bf[nt]);
        }
    };

    // pipeline
    ldg_tile(0);
    sts_tile(0);
    __syncthreads();
    for (int t = 0; t < NT; t++) {
        const int buf = t & 1;
        if (t + 1 < NT) {
            ldg_tile(t + 1);
            compute(buf);
            sts_tile(buf ^ 1);
            __syncthreads();
        } else {
            compute(buf);
        }
    }

    // epilogue: c fragment -> gmem
    const int g   = lane >> 2;
    const int tg2 = (lane & 3) * 2;
    float* Cz = C + (long)z * sC;
    #pragma unroll
    for (int mt = 0; mt < 4; mt++) {
        #pragma unroll
        for (int half = 0; half < 2; half++) {
            const long row = m0 + wm + mt * 16 + g + half * 8;
            float* Crow = Cz + row * (long)N;
            #pragma unroll
            for (int nt = 0; nt < 4; nt++) {
                const long col = n0 + wn + nt * 8 + tg2;
                float2 o;
                o.x = acc[mt][nt][half * 2 + 0] * alpha;
                o.y = acc[mt][nt][half * 2 + 1] * alpha;
                if (bias) {
                    o.x += bias[col + 0];
                    o.y += bias[col + 1];
                }
                *(float2*)(Crow + col) = o;
            }
        }
    }
}

// ---------------------------------------------------------------------------
// fp32 -> bf16 hi/lo split helpers & kernels
// ---------------------------------------------------------------------------
__device__ __forceinline__ void split_store4(__nv_bfloat16* hi, __nv_bfloat16* lo,
                                             long idx, float4 v)
{
    __nv_bfloat16 h0 = __float2bfloat16(v.x);
    __nv_bfloat16 h1 = __float2bfloat16(v.y);
    __nv_bfloat16 h2 = __float2bfloat16(v.z);
    __nv_bfloat16 h3 = __float2bfloat16(v.w);
    *(__nv_bfloat162*)(hi + idx)     = __halves2bfloat162(h0, h1);
    *(__nv_bfloat162*)(hi + idx + 2) = __halves2bfloat162(h2, h3);
    __nv_bfloat16 l0 = __float2bfloat16(v.x - __bfloat162float(h0));
    __nv_bfloat16 l1 = __float2bfloat16(v.y - __bfloat162float(h1));
    __nv_bfloat16 l2 = __float2bfloat16(v.z - __bfloat162float(h2));
    __nv_bfloat16 l3 = __float2bfloat16(v.w - __bfloat162float(h3));
    *(__nv_bfloat162*)(lo + idx)     = __halves2bfloat162(l0, l1);
    *(__nv_bfloat162*)(lo + idx + 2) = __halves2bfloat162(l2, l3);
}

__global__ void __launch_bounds__(256)
split_kernel(const float* __restrict__ in, __nv_bfloat16* __restrict__ hi,
             __nv_bfloat16* __restrict__ lo, long n)
{
    long i = ((long)blockIdx.x * 256 + threadIdx.x) * 4;
    if (i >= n) return;
    float4 f = *(const float4*)(in + i);
    split_store4(hi, lo, i, f);
}

// V [B,S,D] fp32 -> Vt hi/lo [B,D,S] bf16
__global__ void __launch_bounds__(256)
transpose_split_kernel(const float* __restrict__ V,
                       __nv_bfloat16* __restrict__ Thi,
                       __nv_bfloat16* __restrict__ Tlo)
{
    __shared__ float t[32][33];
    const int z  = blockIdx.z;
    const int r0 = blockIdx.y * 32;   // S
    const int c0 = blockIdx.x * 32;   // D
    const int tx = threadIdx.x, ty = threadIdx.y;
    const float* in = V + (long)z * SEQ * DIM;
    __nv_bfloat16* oh = Thi + (long)z * DIM * SEQ;
    __nv_bfloat16* ol = Tlo + (long)z * DIM * SEQ;

    #pragma unroll
    for (int j = 0; j < 4; j++)
        t[ty + 8 * j][tx] = in[(long)(r0 + ty + 8 * j) * DIM + c0 + tx];
    __syncthreads();
    #pragma unroll
    for (int j = 0; j < 4; j++) {
        float val = t[tx][ty + 8 * j];
        long o = (long)(c0 + ty + 8 * j) * SEQ + r0 + tx;
        __nv_bfloat16 h = __float2bfloat16(val);
        oh[o] = h;
        ol[o] = __float2bfloat16(val - __bfloat162float(h));
    }
}

// ---------------------------------------------------------------------------
// Row softmax fused with hi/lo split of attn probabilities.
// ---------------------------------------------------------------------------
__global__ void __launch_bounds__(256)
softmax_split_kernel(const float* __restrict__ S,
                     __nv_bfloat16* __restrict__ Ahi,
                     __nv_bfloat16* __restrict__ Alo)
{
    __shared__ float red[8];
    __shared__ float bcast;

    const long row = blockIdx.x;
    const float4* p4 = (const float4*)(S + row * (long)SEQ);
    const int tid  = threadIdx.x;
    const int lane = tid & 31;
    const int wid  = tid >> 5;

    float4 v0 = p4[tid];
    float4 v1 = p4[tid + 256];

    float m = fmaxf(fmaxf(fmaxf(v0.x, v0.y), fmaxf(v0.z, v0.w)),
                    fmaxf(fmaxf(v1.x, v1.y), fmaxf(v1.z, v1.w)));
    #pragma unroll
    for (int o = 16; o > 0; o >>= 1) m = fmaxf(m, __shfl_xor_sync(0xffffffffu, m, o));
    if (lane == 0) red[wid] = m;
    __syncthreads();
    if (wid == 0) {
        float x = (lane < 8) ? red[lane] : -3.4e38f;
        #pragma unroll
        for (int o = 4; o > 0; o >>= 1) x = fmaxf(x, __shfl_xor_sync(0xffffffffu, x, o));
        if (lane == 0) bcast = x;
    }
    __syncthreads();
    m = bcast;
    __syncthreads();

    v0.x = __expf(v0.x - m); v0.y = __expf(v0.y - m);
    v0.z = __expf(v0.z - m); v0.w = __expf(v0.w - m);
    v1.x = __expf(v1.x - m); v1.y = __expf(v1.y - m);
    v1.z = __expf(v1.z - m); v1.w = __expf(v1.w - m);
    float s = (v0.x + v0.y + v0.z + v0.w) + (v1.x + v1.y + v1.z + v1.w);
    #pragma unroll
    for (int o = 16; o > 0; o >>= 1) s += __shfl_xor_sync(0xffffffffu, s, o);
    if (lane == 0) red[wid] = s;
    __syncthreads();
    if (wid == 0) {
        float x = (lane < 8) ? red[lane] : 0.0f;
        #pragma unroll
        for (int o = 4; o > 0; o >>= 1) x += __shfl_xor_sync(0xffffffffu, x, o);
        if (lane == 0) bcast = x;
    }
    __syncthreads();
    const float inv = 1.0f / bcast;

    v0.x *= inv; v0.y *= inv; v0.z *= inv; v0.w *= inv;
    v1.x *= inv; v1.y *= inv; v1.z *= inv; v1.w *= inv;

    const long base = row * (long)SEQ;
    split_store4(Ahi, Alo, base + tid * 4, v0);
    split_store4(Ahi, Alo, base + 1024 + tid * 4, v1);
}

// ---------------------------------------------------------------------------
// kernel_launch
// inputs: x, Wq, bq, Wk, bk, Wv, bv
// ---------------------------------------------------------------------------
extern "C" void kernel_launch(void* const* d_in, const int* in_sizes, int n_in,
                              void* d_out, int out_size)
{
    const float* x  = (const float*)d_in[0];
    const float* Wq = (const float*)d_in[1];
    const float* bq = (const float*)d_in[2];
    const float* Wk = (const float*)d_in[3];
    const float* bk = (const float*)d_in[4];
    const float* Wv = (const float*)d_in[5];
    const float* bv = (const float*)d_in[6];
    float* out = (float*)d_out;

    __nv_bfloat16 *xhi, *xlo, *whi, *wlo, *qhi, *qlo, *khi, *klo, *vthi, *vtlo, *ahi, *alo;
    float *q, *k, *v, *sc;
    cudaGetSymbolAddress((void**)&xhi,  g_xhi);
    cudaGetSymbolAddress((void**)&xlo,  g_xlo);
    cudaGetSymbolAddress((void**)&whi,  g_whi);
    cudaGetSymbolAddress((void**)&wlo,  g_wlo);
    cudaGetSymbolAddress((void**)&q,    g_q);
    cudaGetSymbolAddress((void**)&k,    g_k);
    cudaGetSymbolAddress((void**)&v,    g_v);
    cudaGetSymbolAddress((void**)&qhi,  g_qhi);
    cudaGetSymbolAddress((void**)&qlo,  g_qlo);
    cudaGetSymbolAddress((void**)&khi,  g_khi);
    cudaGetSymbolAddress((void**)&klo,  g_klo);
    cudaGetSymbolAddress((void**)&vthi, g_vthi);
    cudaGetSymbolAddress((void**)&vtlo, g_vtlo);
    cudaGetSymbolAddress((void**)&sc,   g_s);
    cudaGetSymbolAddress((void**)&ahi,  g_ahi);
    cudaGetSymbolAddress((void**)&alo,  g_alo);

    const long nxd = (long)NROWS * DIM;
    const long nww = (long)DIM * DIM;

    // split inputs
    split_kernel<<<(int)(nxd / 4 / 256), 256>>>(x,  xhi, xlo, nxd);
    split_kernel<<<(int)(nww / 4 / 256), 256>>>(Wq, whi,           wlo,           nww);
    split_kernel<<<(int)(nww / 4 / 256), 256>>>(Wk, whi + nww,     wlo + nww,     nww);
    split_kernel<<<(int)(nww / 4 / 256), 256>>>(Wv, whi + 2 * nww, wlo + 2 * nww, nww);

    // QKV projections: [8192,1024] x W^T + bias
    {
        dim3 grid(NROWS / 128, DIM / 128, 1);
        gemm_bf16x3<<<grid, 256>>>(xhi, xlo, whi,           wlo,           bq, q, DIM, DIM, 0, 0, 0, 1.0f);
        gemm_bf16x3<<<grid, 256>>>(xhi, xlo, whi + nww,     wlo + nww,     bk, k, DIM, DIM, 0, 0, 0, 1.0f);
        gemm_bf16x3<<<grid, 256>>>(xhi, xlo, whi + 2 * nww, wlo + 2 * nww, bv, v, DIM, DIM, 0, 0, 0, 1.0f);
    }

    // split q,k ; transpose-split v
    split_kernel<<<(int)(nxd / 4 / 256), 256>>>(q, qhi, qlo, nxd);
    split_kernel<<<(int)(nxd / 4 / 256), 256>>>(k, khi, klo, nxd);
    {
        dim3 grid(DIM / 32, SEQ / 32, BATCH);
        dim3 blk(32, 8);
        transpose_split_kernel<<<grid, blk>>>(v, vthi, vtlo);
    }

    // scores: per batch [2048,1024] x [2048,1024]^T * 1/32
    {
        dim3 grid(SEQ / 128, SEQ / 128, BATCH);
        gemm_bf16x3<<<grid, 256>>>(qhi, qlo, khi, klo, nullptr, sc,
                                   DIM, SEQ,
                                   (long)SEQ * DIM, (long)SEQ * DIM,
                                   (long)SEQ * SEQ, 1.0f / 32.0f);
    }

    // softmax + split attn
    softmax_split_kernel<<<NROWS, 256>>>(sc, ahi, alo);

    // out: per batch attn[2048,2048] x Vt[1024,2048]^T
    {
        dim3 grid(SEQ / 128, DIM / 128, BATCH);
        gemm_bf16x3<<<grid, 256>>>(ahi, alo, vthi, vtlo, nullptr, out,
                                   SEQ, DIM,
                                   (long)SEQ * SEQ, (long)DIM * SEQ,
                                   (long)SEQ * DIM, 1.0f);
    }
}

// round 7
// speedup vs baseline: 2.1541x; 1.1401x over previous
#include <cuda_runtime.h>
#include <cuda_bf16.h>
#include <stdint.h>
#include <math.h>

// ---------------------------------------------------------------------------
// Problem constants
// ---------------------------------------------------------------------------
#define BATCH 4
#define SEQ   2048
#define DIM   1024
#define NROWS (BATCH * SEQ)          // 8192

// ---------------------------------------------------------------------------
// Scratch (device globals: allocation-free)
// ---------------------------------------------------------------------------
__device__ __align__(128) __nv_bfloat16 g_xhi[(size_t)NROWS * DIM];
__device__ __align__(128) __nv_bfloat16 g_xlo[(size_t)NROWS * DIM];
__device__ __align__(128) __nv_bfloat16 g_whi[(size_t)3 * DIM * DIM];
__device__ __align__(128) __nv_bfloat16 g_wlo[(size_t)3 * DIM * DIM];
__device__ __align__(128) __nv_bfloat16 g_qhi[(size_t)NROWS * DIM];
__device__ __align__(128) __nv_bfloat16 g_qlo[(size_t)NROWS * DIM];
__device__ __align__(128) __nv_bfloat16 g_khi[(size_t)NROWS * DIM];
__device__ __align__(128) __nv_bfloat16 g_klo[(size_t)NROWS * DIM];
__device__ __align__(128) __nv_bfloat16 g_vthi[(size_t)DIM * NROWS];   // [D, B*S]
__device__ __align__(128) __nv_bfloat16 g_vtlo[(size_t)DIM * NROWS];
__device__ __align__(128) float         g_s[(size_t)BATCH * SEQ * SEQ];
__device__ __align__(128) __nv_bfloat16 g_ahi[(size_t)BATCH * SEQ * SEQ];
__device__ __align__(128) __nv_bfloat16 g_alo[(size_t)BATCH * SEQ * SEQ];

// ---------------------------------------------------------------------------
// PTX helpers (baseline PTX only — NO tcgen05: harness ptxas targets sm_103)
// ---------------------------------------------------------------------------
__device__ __forceinline__ uint32_t smem_u32(const void* p) {
    uint32_t a;
    asm("{ .reg .u64 t; cvta.to.shared.u64 t, %1; cvt.u32.u64 %0, t; }"
        : "=r"(a) : "l"(p));
    return a;
}

__device__ __forceinline__ void ldmatrix_x4(uint32_t& r0, uint32_t& r1,
                                            uint32_t& r2, uint32_t& r3,
                                            uint32_t addr) {
    asm volatile("ldmatrix.sync.aligned.m8n8.x4.shared.b16 {%0,%1,%2,%3}, [%4];"
                 : "=r"(r0), "=r"(r1), "=r"(r2), "=r"(r3) : "r"(addr));
}

__device__ __forceinline__ void mma_bf16(float* d, const uint32_t* a,
                                         const uint32_t* b) {
    asm volatile(
        "mma.sync.aligned.m16n8k16.row.col.f32.bf16.bf16.f32 "
        "{%0,%1,%2,%3}, {%4,%5,%6,%7}, {%8,%9}, {%0,%1,%2,%3};"
        : "+f"(d[0]), "+f"(d[1]), "+f"(d[2]), "+f"(d[3])
        : "r"(a[0]), "r"(a[1]), "r"(a[2]), "r"(a[3]),
          "r"(b[0]), "r"(b[1]));
}

#define CP_ASYNC16(smem, gptr) \
    asm volatile("cp.async.cg.shared.global [%0], [%1], 16;" \
                 :: "r"(smem), "l"(gptr) : "memory")
#define CP_COMMIT() asm volatile("cp.async.commit_group;" ::: "memory")
#define CP_WAIT(n)  asm volatile("cp.async.wait_group %0;" :: "n"(n) : "memory")

__device__ __forceinline__ void split2_store(__nv_bfloat16* hi, __nv_bfloat16* lo,
                                             long idx, float v0, float v1)
{
    __nv_bfloat16 h0 = __float2bfloat16(v0);
    __nv_bfloat16 h1 = __float2bfloat16(v1);
    *(__nv_bfloat162*)(hi + idx) = __halves2bfloat162(h0, h1);
    *(__nv_bfloat162*)(lo + idx) = __halves2bfloat162(
        __float2bfloat16(v0 - __bfloat162float(h0)),
        __float2bfloat16(v1 - __bfloat162float(h1)));
}

// ---------------------------------------------------------------------------
// bf16x3 GEMM via mma.sync + cp.async 4-stage pipeline.
//   C[m,n] = alpha * sum_k A[m,k]*B[n,k] (+ bias)
//   A ~ Ahi+Alo rm [M,K] lda; B ~ Bhi+Blo rm [N,K] ldb; K logically tripled
//   via 3 segments (hi,hi),(hi,lo),(lo,hi) into one fp32 accumulator.
//   Tile 128x128, BK=32, 256 thr = 8 warps (2m x 4n), warp tile 64x32.
//   smem rows padded to 40 elems (80B = 5*16B): aligned + conflict-free.
// EPI: 0 = fp32 out (alpha, no bias)
//      1 = bf16 hi/lo split out, column bias
//      2 = bf16 hi/lo split out, row bias
// ---------------------------------------------------------------------------
#define PAD    40
#define SMB    (128 * PAD * 2)   // bytes per stage per matrix (10240)
#define NSTAGE 4
#define SMEM_TOTAL (2 * NSTAGE * SMB)   // 81920

template <int EPI>
__global__ void __launch_bounds__(256, 2)
gemm_bf16x3(const __nv_bfloat16* __restrict__ Ahi, const __nv_bfloat16* __restrict__ Alo,
            const __nv_bfloat16* __restrict__ Bhi, const __nv_bfloat16* __restrict__ Blo,
            const float* __restrict__ bias,
            float* __restrict__ Cf,
            __nv_bfloat16* __restrict__ Chi, __nv_bfloat16* __restrict__ Clo,
            int K, int lda, int ldb, int ldc,
            long sA, long sB, long sC, float alpha)
{
    extern __shared__ __align__(128) char dsm[];
    const uint32_t sa_base = smem_u32(dsm);
    const uint32_t sb_base = sa_base + NSTAGE * SMB;

    const int tid  = threadIdx.x;
    const int lane = tid & 31;
    const int wid  = tid >> 5;
    const int wm   = (wid >> 2) * 64;   // warp m origin (0 or 64)
    const int wn   = (wid & 3) * 32;    // warp n origin (0,32,64,96)

    const long m0 = (long)blockIdx.x * 128;
    const long n0 = (long)blockIdx.y * 128;
    const int  z  = blockIdx.z;
    const int  KT = K >> 5;             // 32-wide K tiles per segment
    const int  NT = 3 * KT;

    const __nv_bfloat16* Ah = Ahi + (long)z * sA;
    const __nv_bfloat16* Al = Alo + (long)z * sA;
    const __nv_bfloat16* Bh = Bhi + (long)z * sB;
    const __nv_bfloat16* Bl = Blo + (long)z * sB;

    float acc[4][4][4];
    #pragma unroll
    for (int i = 0; i < 4; i++)
        #pragma unroll
        for (int j = 0; j < 4; j++)
            #pragma unroll
            for (int r = 0; r < 4; r++) acc[i][j][r] = 0.0f;

    // per-thread load slots: 2 x (row, k-chunk) covering 128x32 per matrix
    const int r0_ = tid >> 2;           // 0..63
    const int j0_ = tid & 3;
    // second slot: id = tid + 256 -> row = 64 + r0_, same j

    auto issue_tile = [&](int t, int buf) {
        const int seg = t / KT;
        const long kk = (long)(t - seg * KT) << 5;
        const __nv_bfloat16* Ap = (seg < 2)  ? Ah : Al;
        const __nv_bfloat16* Bp = (seg != 1) ? Bh : Bl;
        const uint32_t sa = sa_base + buf * SMB;
        const uint32_t sb = sb_base + buf * SMB;
        #pragma unroll
        for (int i = 0; i < 2; i++) {
            const int row = r0_ + i * 64;
            const uint32_t so = (uint32_t)(row * PAD + j0_ * 8) * 2;
            CP_ASYNC16(sa + so, Ap + (m0 + row) * (long)lda + kk + j0_ * 8);
            CP_ASYNC16(sb + so, Bp + (n0 + row) * (long)ldb + kk + j0_ * 8);
        }
        CP_COMMIT();
    };

    auto compute = [&](int buf) {
        const uint32_t ab = sa_base + buf * SMB;
        const uint32_t bb = sb_base + buf * SMB;
        #pragma unroll
        for (int ks = 0; ks < 2; ks++) {
            uint32_t af[4][4], bf[4][2];
            #pragma unroll
            for (int mt = 0; mt < 4; mt++) {
                const int row  = wm + mt * 16 + (lane & 15);
                const int koff = ks * 16 + ((lane >> 4) << 3);
                ldmatrix_x4(af[mt][0], af[mt][1], af[mt][2], af[mt][3],
                            ab + (row * PAD + koff) * 2);
            }
            #pragma unroll
            for (int h = 0; h < 2; h++) {
                const int row  = wn + h * 16 + (lane & 7) + ((lane >> 4) << 3);
                const int koff = ks * 16 + ((lane >> 3) & 1) * 8;
                ldmatrix_x4(bf[h * 2][0], bf[h * 2][1],
                            bf[h * 2 + 1][0], bf[h * 2 + 1][1],
                            bb + (row * PAD + koff) * 2);
            }
            #pragma unroll
            for (int mt = 0; mt < 4; mt++)
                #pragma unroll
                for (int nt = 0; nt < 4; nt++)
                    mma_bf16(acc[mt][nt], af[mt], bf[nt]);
        }
    };

    // 4-stage pipeline, one barrier per iteration.
    // issue at iter t overwrites buf (t-1)&3, whose readers (compute(t-1))
    // all passed this iteration's __syncthreads.
    #pragma unroll
    for (int s = 0; s < NSTAGE - 1; s++) issue_tile(s, s);
    for (int t = 0; t < NT; t++) {
        CP_WAIT(NSTAGE - 2);
        __syncthreads();
        if (t + NSTAGE - 1 < NT) issue_tile(t + NSTAGE - 1, (t + NSTAGE - 1) & 3);
        compute(t & 3);
    }

    // epilogue
    const int g   = lane >> 2;
    const int tg2 = (lane & 3) * 2;
    #pragma unroll
    for (int mt = 0; mt < 4; mt++) {
        #pragma unroll
        for (int half = 0; half < 2; half++) {
            const long row = m0 + wm + mt * 16 + g + half * 8;
            const long rbase = (long)z * sC + row * (long)ldc;
            #pragma unroll
            for (int nt = 0; nt < 4; nt++) {
                const long col = n0 + wn + nt * 8 + tg2;
                float v0 = acc[mt][nt][half * 2 + 0] * alpha;
                float v1 = acc[mt][nt][half * 2 + 1] * alpha;
                if (EPI == 0) {
                    *(float2*)(Cf + rbase + col) = make_float2(v0, v1);
                } else if (EPI == 1) {
                    v0 += bias[col];
                    v1 += bias[col + 1];
                    split2_store(Chi, Clo, rbase + col, v0, v1);
                } else {
                    const float b = bias[row];
                    split2_store(Chi, Clo, rbase + col, v0 + b, v1 + b);
                }
            }
        }
    }
}

// ---------------------------------------------------------------------------
// fp32 -> bf16 hi/lo split (x and W pre-passes)
// ---------------------------------------------------------------------------
__device__ __forceinline__ void split_store4(__nv_bfloat16* hi, __nv_bfloat16* lo,
                                             long idx, float4 v)
{
    split2_store(hi, lo, idx,     v.x, v.y);
    split2_store(hi, lo, idx + 2, v.z, v.w);
}

__global__ void __launch_bounds__(256)
split_kernel(const float* __restrict__ in, __nv_bfloat16* __restrict__ hi,
             __nv_bfloat16* __restrict__ lo, long n)
{
    long i = ((long)blockIdx.x * 256 + threadIdx.x) * 4;
    if (i >= n) return;
    float4 f = *(const float4*)(in + i);
    split_store4(hi, lo, i, f);
}

// ---------------------------------------------------------------------------
// Row softmax fused with hi/lo split of attn probabilities.
// ---------------------------------------------------------------------------
__global__ void __launch_bounds__(256)
softmax_split_kernel(const float* __restrict__ S,
                     __nv_bfloat16* __restrict__ Ahi,
                     __nv_bfloat16* __restrict__ Alo)
{
    __shared__ float red[8];
    __shared__ float bcast;

    const long row = blockIdx.x;
    const float4* p4 = (const float4*)(S + row * (long)SEQ);
    const int tid  = threadIdx.x;
    const int lane = tid & 31;
    const int wid  = tid >> 5;

    float4 v0 = p4[tid];
    float4 v1 = p4[tid + 256];

    float m = fmaxf(fmaxf(fmaxf(v0.x, v0.y), fmaxf(v0.z, v0.w)),
                    fmaxf(fmaxf(v1.x, v1.y), fmaxf(v1.z, v1.w)));
    #pragma unroll
    for (int o = 16; o > 0; o >>= 1) m = fmaxf(m, __shfl_xor_sync(0xffffffffu, m, o));
    if (lane == 0) red[wid] = m;
    __syncthreads();
    if (wid == 0) {
        float x = (lane < 8) ? red[lane] : -3.4e38f;
        #pragma unroll
        for (int o = 4; o > 0; o >>= 1) x = fmaxf(x, __shfl_xor_sync(0xffffffffu, x, o));
        if (lane == 0) bcast = x;
    }
    __syncthreads();
    m = bcast;
    __syncthreads();

    v0.x = __expf(v0.x - m); v0.y = __expf(v0.y - m);
    v0.z = __expf(v0.z - m); v0.w = __expf(v0.w - m);
    v1.x = __expf(v1.x - m); v1.y = __expf(v1.y - m);
    v1.z = __expf(v1.z - m); v1.w = __expf(v1.w - m);
    float s = (v0.x + v0.y + v0.z + v0.w) + (v1.x + v1.y + v1.z + v1.w);
    #pragma unroll
    for (int o = 16; o > 0; o >>= 1) s += __shfl_xor_sync(0xffffffffu, s, o);
    if (lane == 0) red[wid] = s;
    __syncthreads();
    if (wid == 0) {
        float x = (lane < 8) ? red[lane] : 0.0f;
        #pragma unroll
        for (int o = 4; o > 0; o >>= 1) x += __shfl_xor_sync(0xffffffffu, x, o);
        if (lane == 0) bcast = x;
    }
    __syncthreads();
    const float inv = 1.0f / bcast;

    v0.x *= inv; v0.y *= inv; v0.z *= inv; v0.w *= inv;
    v1.x *= inv; v1.y *= inv; v1.z *= inv; v1.w *= inv;

    const long base = row * (long)SEQ;
    split_store4(Ahi, Alo, base + tid * 4, v0);
    split_store4(Ahi, Alo, base + 1024 + tid * 4, v1);
}

// ---------------------------------------------------------------------------
// kernel_launch
// inputs: x, Wq, bq, Wk, bk, Wv, bv
// ---------------------------------------------------------------------------
extern "C" void kernel_launch(void* const* d_in, const int* in_sizes, int n_in,
                              void* d_out, int out_size)
{
    const float* x  = (const float*)d_in[0];
    const float* Wq = (const float*)d_in[1];
    const float* bq = (const float*)d_in[2];
    const float* Wk = (const float*)d_in[3];
    const float* bk = (const float*)d_in[4];
    const float* Wv = (const float*)d_in[5];
    const float* bv = (const float*)d_in[6];
    float* out = (float*)d_out;

    __nv_bfloat16 *xhi, *xlo, *whi, *wlo, *qhi, *qlo, *khi, *klo, *vthi, *vtlo, *ahi, *alo;
    float *sc;
    cudaGetSymbolAddress((void**)&xhi,  g_xhi);
    cudaGetSymbolAddress((void**)&xlo,  g_xlo);
    cudaGetSymbolAddress((void**)&whi,  g_whi);
    cudaGetSymbolAddress((void**)&wlo,  g_wlo);
    cudaGetSymbolAddress((void**)&qhi,  g_qhi);
    cudaGetSymbolAddress((void**)&qlo,  g_qlo);
    cudaGetSymbolAddress((void**)&khi,  g_khi);
    cudaGetSymbolAddress((void**)&klo,  g_klo);
    cudaGetSymbolAddress((void**)&vthi, g_vthi);
    cudaGetSymbolAddress((void**)&vtlo, g_vtlo);
    cudaGetSymbolAddress((void**)&sc,   g_s);
    cudaGetSymbolAddress((void**)&ahi,  g_ahi);
    cudaGetSymbolAddress((void**)&alo,  g_alo);

    cudaFuncSetAttribute(gemm_bf16x3<0>, cudaFuncAttributeMaxDynamicSharedMemorySize, SMEM_TOTAL);
    cudaFuncSetAttribute(gemm_bf16x3<1>, cudaFuncAttributeMaxDynamicSharedMemorySize, SMEM_TOTAL);
    cudaFuncSetAttribute(gemm_bf16x3<2>, cudaFuncAttributeMaxDynamicSharedMemorySize, SMEM_TOTAL);

    const long nxd = (long)NROWS * DIM;
    const long nww = (long)DIM * DIM;

    // split inputs (x and weights only; q/k/v splits are fused into epilogues)
    split_kernel<<<(int)(nxd / 4 / 256), 256>>>(x,  xhi, xlo, nxd);
    split_kernel<<<(int)(nww / 4 / 256), 256>>>(Wq, whi,           wlo,           nww);
    split_kernel<<<(int)(nww / 4 / 256), 256>>>(Wk, whi + nww,     wlo + nww,     nww);
    split_kernel<<<(int)(nww / 4 / 256), 256>>>(Wv, whi + 2 * nww, wlo + 2 * nww, nww);

    // Q, K projections: [8192,1024] x W^T + colbias -> split bf16 [8192,1024]
    {
        dim3 grid(NROWS / 128, DIM / 128, 1);
        gemm_bf16x3<1><<<grid, 256, SMEM_TOTAL>>>(xhi, xlo, whi,       wlo,       bq,
                                                  nullptr, qhi, qlo,
                                                  DIM, DIM, DIM, DIM, 0, 0, 0, 1.0f);
        gemm_bf16x3<1><<<grid, 256, SMEM_TOTAL>>>(xhi, xlo, whi + nww, wlo + nww, bk,
                                                  nullptr, khi, klo,
                                                  DIM, DIM, DIM, DIM, 0, 0, 0, 1.0f);
    }
    // V projection, transposed: Vt[d, s] = sum_k Wv[d,k] x[s,k] + bv[d]
    //   A = Wv [1024,1024], B = x [8192,1024], C = Vt [1024, 8192], row bias
    {
        dim3 grid(DIM / 128, NROWS / 128, 1);
        gemm_bf16x3<2><<<grid, 256, SMEM_TOTAL>>>(whi + 2 * nww, wlo + 2 * nww, xhi, xlo, bv,
                                                  nullptr, vthi, vtlo,
                                                  DIM, DIM, DIM, NROWS, 0, 0, 0, 1.0f);
    }

    // scores: per batch [2048,1024] x [2048,1024]^T * 1/32 -> fp32
    {
        dim3 grid(SEQ / 128, SEQ / 128, BATCH);
        gemm_bf16x3<0><<<grid, 256, SMEM_TOTAL>>>(qhi, qlo, khi, klo, nullptr,
                                                  sc, nullptr, nullptr,
                                                  DIM, DIM, DIM, SEQ,
                                                  (long)SEQ * DIM, (long)SEQ * DIM,
                                                  (long)SEQ * SEQ, 1.0f / 32.0f);
    }

    // softmax + split attn
    softmax_split_kernel<<<NROWS, 256>>>(sc, ahi, alo);

    // out: per batch attn[2048,2048] x Vt[:, b*2048 : b*2048+2048]^T -> fp32
    //   B = Vt [1024 rows, ldb=8192], batch offset = 2048 columns (k offset)
    {
        dim3 grid(SEQ / 128, DIM / 128, BATCH);
        gemm_bf16x3<0><<<grid, 256, SMEM_TOTAL>>>(ahi, alo, vthi, vtlo, nullptr,
                                                  out, nullptr, nullptr,
                                                  SEQ, SEQ, NROWS, DIM,
                                                  (long)SEQ * SEQ, (long)SEQ,
                                                  (long)SEQ * DIM, 1.0f);
    }
}